// round 15
// baseline (speedup 1.0000x reference)
#include <cuda_runtime.h>
#include <cuda_bf16.h>
#include <cstdint>

// Problem constants (fixed by setup_inputs): T=128, N=2048, D=256, w=3
#define T_SNAP 128
#define N_NODE 2048
#define D_HID  256
#define WIN    3
#define ROWS   (T_SNAP * N_NODE)   // 262144

// Scratch (allocation-free rule: __device__ globals)
__device__ float g_score[ROWS];
__device__ float g_p[ROWS];
// Pre-packed W: g_Wb[kk*256 + n] = bf16x2{ W[2kk][n], W[2kk+1][n] }, kk=0..127
__device__ uint32_t g_Wb[128 * 256];   // 128 KB

// ---------------------------------------------------------------------------
__device__ __forceinline__ uint32_t pack_bf16(float lo, float hi) {
    __nv_bfloat162 h = __floats2bfloat162_rn(lo, hi);
    return *reinterpret_cast<uint32_t*>(&h);
}

__device__ __forceinline__ void mma_bf16(float* c, const uint32_t* a, const uint32_t* b) {
    asm volatile(
        "mma.sync.aligned.m16n8k16.row.col.f32.bf16.bf16.f32 "
        "{%0,%1,%2,%3}, {%4,%5,%6,%7}, {%8,%9}, {%0,%1,%2,%3};"
        : "+f"(c[0]), "+f"(c[1]), "+f"(c[2]), "+f"(c[3])
        : "r"(a[0]), "r"(a[1]), "r"(a[2]), "r"(a[3]), "r"(b[0]), "r"(b[1]));
}

__device__ __forceinline__ void cp_async16(uint32_t smem_dst, const void* gptr) {
    asm volatile("cp.async.cg.shared.global [%0], [%1], 16;"
                 :: "r"(smem_dst), "l"(gptr) : "memory");
}
__device__ __forceinline__ void cp_commit() {
    asm volatile("cp.async.commit_group;" ::: "memory");
}
__device__ __forceinline__ void cp_wait_all() {
    asm volatile("cp.async.wait_group 0;" ::: "memory");
}

// ---------------------------------------------------------------------------
// Kernel 0: pack W into bf16x2 [kk][n] layout (one-shot, ~µs)
// ---------------------------------------------------------------------------
__global__ __launch_bounds__(256) void prep_w_kernel(const float* __restrict__ W)
{
    int idx = blockIdx.x * 256 + threadIdx.x;  // 0..32767
    int n  = idx & 255;
    int kk = idx >> 8;                         // global k-pair 0..127
    g_Wb[idx] = pack_bf16(W[(2 * kk) * D_HID + n], W[(2 * kk + 1) * D_HID + n]);
}

// ---------------------------------------------------------------------------
// Kernel 1 (mma.sync bf16): score[row] = proj . tanh( X[row,:] @ W )
// Block: 256 threads = 8 warps, 2(M) x 4(N). Tile M=64, N=256, BK=64 x 4.
// A: FULL-K resident tile (64 x 128 k2, stride 132 -> (4r+q)%32 conflict-free)
//    staged ONCE in the prologue, overlapping B(0)'s cp.async.
// B: double-buffered cp.async from pre-packed g_Wb (L2-hot).
// Mainloop: wait-B -> stageB(c+1) -> 64 MMAs/warp. No A traffic in loop.
// Smem 103.4 KB -> 2 CTAs/SM.
// ---------------------------------------------------------------------------
#define A_STRIDE 132    // u32: banks (132r+q)%32 = (4r+q)%32 all distinct
#define BS_STRIDE 264   // u32: banks (8*qlane+qid)%32 all distinct
#define A_BYTES (64 * A_STRIDE * 4)      // 33792
#define B_BUF   (32 * BS_STRIDE * 4)     // 33792
#define A_OFF    0
#define B_OFF    A_BYTES                 // 33792
#define PROJ_OFF (B_OFF + 2 * B_BUF)     // 101376
#define PART_OFF (PROJ_OFF + 1024)       // 102400
#define SC_SMEM  (PART_OFF + 1024)       // 103424

__global__ __launch_bounds__(256, 2) void score_kernel(
    const float4* __restrict__ X4,
    const float*  __restrict__ proj)
{
    extern __shared__ char smem[];
    const uint32_t sb = (uint32_t)__cvta_generic_to_shared(smem);
    uint32_t* Asm = (uint32_t*)(smem + A_OFF);
    uint32_t* Bsm = (uint32_t*)(smem + B_OFF);
    float* sproj  = (float*)(smem + PROJ_OFF);
    float* part   = (float*)(smem + PART_OFF);   // [4][64]

    const int tid    = threadIdx.x;
    const int lane   = tid & 31;
    const int wid    = tid >> 5;
    const int warp_m = wid >> 2;
    const int warp_n = wid & 3;
    const int qid    = lane >> 2;
    const int qlane  = lane & 3;
    const int row0   = blockIdx.x * 64;

    sproj[tid] = proj[tid];

    float acc[2][8][4];
    #pragma unroll
    for (int mt = 0; mt < 2; mt++)
        #pragma unroll
        for (int nt = 0; nt < 8; nt++)
            #pragma unroll
            for (int i = 0; i < 4; i++) acc[mt][nt][i] = 0.0f;

    auto stageB = [&](int c, int bf) {
        #pragma unroll
        for (int i = 0; i < 8; i++) {
            int seg = tid + i * 256;             // 0..2047
            int k2  = seg >> 6;                  // 0..31
            int ng  = seg & 63;                  // float4-col 0..63
            cp_async16(sb + B_OFF + bf * B_BUF + (k2 * BS_STRIDE + ng * 4) * 4,
                       &g_Wb[(c * 32 + k2) * 256 + ng * 4]);
        }
    };

    // ---- Prologue: B(0) in flight, then stage the FULL A tile over it ----
    stageB(0, 0); cp_commit();

    #pragma unroll 4
    for (int i = 0; i < 16; i++) {
        int seg = tid + i * 256;                 // 0..4095
        int m   = seg >> 6;                      // row 0..63
        int c4  = seg & 63;                      // float4-col 0..63
        float4 v = X4[(row0 + m) * 64 + c4];
        uint2 u;
        u.x = pack_bf16(v.x, v.y);
        u.y = pack_bf16(v.z, v.w);
        *reinterpret_cast<uint2*>(&Asm[m * A_STRIDE + c4 * 2]) = u;
    }

    cp_wait_all();
    __syncthreads();

    #pragma unroll 1
    for (int c = 0; c < 4; ++c) {
        const int buf = c & 1;
        const int nxt = buf ^ 1;

        if (c < 3) { stageB(c + 1, nxt); cp_commit(); }

        const uint32_t* Ab = Asm;
        const uint32_t* Bb = Bsm + buf * (B_BUF / 4);
        #pragma unroll
        for (int ks = 0; ks < 4; ks++) {
            const int k2b = c * 32 + ks * 8;     // within the full A row
            const int bk2 = ks * 8;              // within the B buffer
            uint32_t a[2][4];
            #pragma unroll
            for (int mt = 0; mt < 2; mt++) {
                int r = warp_m * 32 + mt * 16 + qid;
                a[mt][0] = Ab[r * A_STRIDE + k2b + qlane];
                a[mt][1] = Ab[(r + 8) * A_STRIDE + k2b + qlane];
                a[mt][2] = Ab[r * A_STRIDE + k2b + qlane + 4];
                a[mt][3] = Ab[(r + 8) * A_STRIDE + k2b + qlane + 4];
            }
            uint32_t b[8][2];
            #pragma unroll
            for (int nt = 0; nt < 8; nt++) {
                int n = warp_n * 64 + nt * 8 + qid;
                b[nt][0] = Bb[(bk2 + qlane)     * BS_STRIDE + n];
                b[nt][1] = Bb[(bk2 + qlane + 4) * BS_STRIDE + n];
            }
            #pragma unroll
            for (int mt = 0; mt < 2; mt++)
                #pragma unroll
                for (int nt = 0; nt < 8; nt++)
                    mma_bf16(acc[mt][nt], a[mt], b[nt]);
        }

        if (c < 3) {
            cp_wait_all();
            __syncthreads();
        }
    }

    // Fused epilogue: per-row sum of tanh(u)*proj over this warp's 64 cols.
    float psum[2][2];
    psum[0][0] = psum[0][1] = psum[1][0] = psum[1][1] = 0.0f;
    #pragma unroll
    for (int mt = 0; mt < 2; mt++)
        #pragma unroll
        for (int nt = 0; nt < 8; nt++) {
            int cb = warp_n * 64 + nt * 8 + 2 * qlane;
            float p0 = sproj[cb], p1 = sproj[cb + 1];
            psum[mt][0] += tanhf(acc[mt][nt][0]) * p0 + tanhf(acc[mt][nt][1]) * p1;
            psum[mt][1] += tanhf(acc[mt][nt][2]) * p0 + tanhf(acc[mt][nt][3]) * p1;
        }
    #pragma unroll
    for (int off = 1; off < 4; off <<= 1) {
        #pragma unroll
        for (int mt = 0; mt < 2; mt++) {
            psum[mt][0] += __shfl_xor_sync(0xffffffffu, psum[mt][0], off);
            psum[mt][1] += __shfl_xor_sync(0xffffffffu, psum[mt][1], off);
        }
    }
    __syncthreads();
    if (qlane == 0) {
        #pragma unroll
        for (int mt = 0; mt < 2; mt++) {
            part[warp_n * 64 + warp_m * 32 + mt * 16 + qid]     = psum[mt][0];
            part[warp_n * 64 + warp_m * 32 + mt * 16 + qid + 8] = psum[mt][1];
        }
    }
    __syncthreads();
    if (tid < 64)
        g_score[row0 + tid] = part[tid] + part[64 + tid] +
                              part[128 + tid] + part[192 + tid];
}

// ---------------------------------------------------------------------------
// Kernel 2: p[j,:] = softmax over N of score[j,:]   (one block per row j)
// ---------------------------------------------------------------------------
__global__ __launch_bounds__(256) void softmax_kernel()
{
    __shared__ float red_max[8];
    __shared__ float red_sum[8];
    const int j   = blockIdx.x;
    const int tid = threadIdx.x;
    const float* row = g_score + j * N_NODE;

    float v[8];
    float m = -1e30f;
    #pragma unroll
    for (int i = 0; i < 8; i++) {
        v[i] = row[tid + i * 256];
        m = fmaxf(m, v[i]);
    }
    #pragma unroll
    for (int off = 16; off > 0; off >>= 1)
        m = fmaxf(m, __shfl_xor_sync(0xffffffffu, m, off));
    if ((tid & 31) == 0) red_max[tid >> 5] = m;
    __syncthreads();
    float bm = red_max[0];
    #pragma unroll
    for (int wq = 1; wq < 8; wq++) bm = fmaxf(bm, red_max[wq]);

    float s = 0.0f;
    #pragma unroll
    for (int i = 0; i < 8; i++) {
        v[i] = expf(v[i] - bm);
        s += v[i];
    }
    #pragma unroll
    for (int off = 16; off > 0; off >>= 1)
        s += __shfl_xor_sync(0xffffffffu, s, off);
    if ((tid & 31) == 0) red_sum[tid >> 5] = s;
    __syncthreads();
    float bs = 0.0f;
    #pragma unroll
    for (int wq = 0; wq < 8; wq++) bs += red_sum[wq];
    float inv = 1.0f / bs;

    #pragma unroll
    for (int i = 0; i < 8; i++)
        g_p[j * N_NODE + tid + i * 256] = v[i] * inv;
}

// ---------------------------------------------------------------------------
// Kernel 3: out (best measured: 78.8 µs — at the traffic floor, FROZEN).
// ---------------------------------------------------------------------------
__global__ __launch_bounds__(256) void out_kernel(
    const float4* __restrict__ X4,
    float4* __restrict__ out4)
{
    const int STRIDE_T = N_NODE * 64;           // float4 per snapshot
    const int i  = blockIdx.x >> 7;             // snapshot 0..127
    const int n  = ((blockIdx.x & 127) << 4) + (threadIdx.x >> 4);
    const int dp = threadIdx.x & 15;
    const int base = (i * N_NODE + n) * 64;

    if (i < WIN) {
        #pragma unroll
        for (int q = 0; q < 4; q++)
            out4[base + dp + q * 16] = X4[base + dp + q * 16];
    } else {
        const int pb = (i - 3) * N_NODE + n;
        const float p0 = g_p[pb];
        const float p1 = g_p[pb + N_NODE];
        const float p2 = g_p[pb + 2 * N_NODE];
        #pragma unroll
        for (int q = 0; q < 4; q++) {
            int d = base + dp + q * 16;
            float4 a = X4[d - 3 * STRIDE_T];
            float4 b = X4[d - 2 * STRIDE_T];
            float4 c = X4[d - 1 * STRIDE_T];
            float4 o;
            o.x = p0 * a.x + p1 * b.x + p2 * c.x;
            o.y = p0 * a.y + p1 * b.y + p2 * c.y;
            o.z = p0 * a.z + p1 * b.z + p2 * c.z;
            o.w = p0 * a.w + p1 * b.w + p2 * c.w;
            out4[d] = o;
        }
    }
}

// ---------------------------------------------------------------------------
extern "C" void kernel_launch(void* const* d_in, const int* in_sizes, int n_in,
                              void* d_out, int out_size)
{
    const float* X    = (const float*)d_in[0];  // (128, 2048, 256)
    const float* W    = (const float*)d_in[1];  // (256, 256)
    const float* proj = (const float*)d_in[2];  // (256, 1)
    float* out        = (float*)d_out;

    cudaFuncSetAttribute(score_kernel,
                         cudaFuncAttributeMaxDynamicSharedMemorySize, SC_SMEM);

    prep_w_kernel<<<128, 256>>>(W);
    score_kernel<<<ROWS / 64, 256, SC_SMEM>>>((const float4*)X, proj);
    softmax_kernel<<<T_SNAP, 256>>>();
    out_kernel<<<T_SNAP * 128, 256>>>((const float4*)X, (float4*)out);
}

// round 16
// speedup vs baseline: 1.0954x; 1.0954x over previous
#include <cuda_runtime.h>
#include <cuda_bf16.h>
#include <cstdint>

// Problem constants (fixed by setup_inputs): T=128, N=2048, D=256, w=3
#define T_SNAP 128
#define N_NODE 2048
#define D_HID  256
#define WIN    3
#define ROWS   (T_SNAP * N_NODE)   // 262144

// Scratch (allocation-free rule: __device__ globals)
__device__ float g_score[ROWS];
__device__ float g_p[ROWS];
// Pre-packed W: g_Wb[kk*256 + n] = bf16x2{ W[2kk][n], W[2kk+1][n] }, kk=0..127
__device__ uint32_t g_Wb[128 * 256];   // 128 KB

// ---------------------------------------------------------------------------
__device__ __forceinline__ uint32_t pack_bf16(float lo, float hi) {
    __nv_bfloat162 h = __floats2bfloat162_rn(lo, hi);
    return *reinterpret_cast<uint32_t*>(&h);
}

// Fast tanh: 1 - 2/(e^{2x}+1). MUFU-based (~6 instr vs ~18 for tanhf).
// Saturates correctly: x>>0 -> exp=inf -> 1;  x<<0 -> exp=0 -> -1.
__device__ __forceinline__ float fast_tanh(float x) {
    float t = __expf(2.0f * x);
    return 1.0f - __fdividef(2.0f, t + 1.0f);
}

__device__ __forceinline__ void mma_bf16(float* c, const uint32_t* a, const uint32_t* b) {
    asm volatile(
        "mma.sync.aligned.m16n8k16.row.col.f32.bf16.bf16.f32 "
        "{%0,%1,%2,%3}, {%4,%5,%6,%7}, {%8,%9}, {%0,%1,%2,%3};"
        : "+f"(c[0]), "+f"(c[1]), "+f"(c[2]), "+f"(c[3])
        : "r"(a[0]), "r"(a[1]), "r"(a[2]), "r"(a[3]), "r"(b[0]), "r"(b[1]));
}

__device__ __forceinline__ void cp_async16(uint32_t smem_dst, const void* gptr) {
    asm volatile("cp.async.cg.shared.global [%0], [%1], 16;"
                 :: "r"(smem_dst), "l"(gptr) : "memory");
}
__device__ __forceinline__ void cp_commit() {
    asm volatile("cp.async.commit_group;" ::: "memory");
}
__device__ __forceinline__ void cp_wait_all() {
    asm volatile("cp.async.wait_group 0;" ::: "memory");
}

// ---------------------------------------------------------------------------
// Kernel 0: pack W into bf16x2 [kk][n] layout (one-shot, ~µs)
// ---------------------------------------------------------------------------
__global__ __launch_bounds__(256) void prep_w_kernel(const float* __restrict__ W)
{
    int idx = blockIdx.x * 256 + threadIdx.x;  // 0..32767
    int n  = idx & 255;
    int kk = idx >> 8;                         // global k-pair 0..127
    g_Wb[idx] = pack_bf16(W[(2 * kk) * D_HID + n], W[(2 * kk + 1) * D_HID + n]);
}

// ---------------------------------------------------------------------------
// Kernel 1 (mma.sync bf16, R14-best schedule: BK=64 x 4, double buffer):
//   score[row] = proj . tanh( X[row,:] @ W )
// Block: 256 threads = 8 warps, 2(M) x 4(N). Tile M=64, N=256.
// B via cp.async from pre-packed g_Wb (L2-hot); A LDG->pack->STS overlapped
// with the 64-MMA compute block. 2 CTAs/SM. Fast-tanh epilogue.
// ---------------------------------------------------------------------------
#define AS_STRIDE 36    // u32: banks (36r+q)%32 = (4r+q)%32 all distinct
#define BS_STRIDE 264   // u32: banks (8*qlane+qid)%32 all distinct
#define A_BUF (64 * AS_STRIDE * 4)       // 9216 B
#define B_BUF (32 * BS_STRIDE * 4)       // 33792 B
#define A_OFF    0
#define B_OFF    (2 * A_BUF)             // 18432
#define PROJ_OFF (B_OFF + 2 * B_BUF)     // 86016
#define PART_OFF (PROJ_OFF + 1024)       // 87040
#define SC_SMEM  (PART_OFF + 1024)       // 88064

__global__ __launch_bounds__(256, 2) void score_kernel(
    const float4* __restrict__ X4,
    const float*  __restrict__ proj)
{
    extern __shared__ char smem[];
    const uint32_t sb = (uint32_t)__cvta_generic_to_shared(smem);
    uint32_t* Asm = (uint32_t*)(smem + A_OFF);
    uint32_t* Bsm = (uint32_t*)(smem + B_OFF);
    float* sproj  = (float*)(smem + PROJ_OFF);
    float* part   = (float*)(smem + PART_OFF);   // [4][64]

    const int tid    = threadIdx.x;
    const int lane   = tid & 31;
    const int wid    = tid >> 5;
    const int warp_m = wid >> 2;
    const int warp_n = wid & 3;
    const int qid    = lane >> 2;
    const int qlane  = lane & 3;
    const int row0   = blockIdx.x * 64;

    sproj[tid] = proj[tid];

    // A staging coords: 1024 float4 segments per chunk, 4 per thread
    int amr[4], acr[4];
    #pragma unroll
    for (int i = 0; i < 4; i++) {
        int seg = tid + i * 256;                 // 0..1023
        amr[i] = seg >> 4;                       // row 0..63
        acr[i] = seg & 15;                       // float4-col within chunk
    }

    float acc[2][8][4];
    #pragma unroll
    for (int mt = 0; mt < 2; mt++)
        #pragma unroll
        for (int nt = 0; nt < 8; nt++)
            #pragma unroll
            for (int i = 0; i < 4; i++) acc[mt][nt][i] = 0.0f;

    auto stageB = [&](int c, int bf) {
        #pragma unroll
        for (int i = 0; i < 8; i++) {
            int seg = tid + i * 256;             // 0..2047
            int k2  = seg >> 6;                  // 0..31
            int ng  = seg & 63;                  // float4-col 0..63
            cp_async16(sb + B_OFF + bf * B_BUF + (k2 * BS_STRIDE + ng * 4) * 4,
                       &g_Wb[(c * 32 + k2) * 256 + ng * 4]);
        }
    };
    auto stsA = [&](int bf, const float4* v) {
        #pragma unroll
        for (int i = 0; i < 4; i++) {
            uint2 u;
            u.x = pack_bf16(v[i].x, v[i].y);
            u.y = pack_bf16(v[i].z, v[i].w);
            *reinterpret_cast<uint2*>(
                &Asm[bf * (A_BUF / 4) + amr[i] * AS_STRIDE + acr[i] * 2]) = u;
        }
    };

    // ---- Prologue: stage chunk 0 ----
    float4 pa[4];
    #pragma unroll
    for (int i = 0; i < 4; i++)
        pa[i] = X4[(row0 + amr[i]) * 64 + acr[i]];
    stageB(0, 0); cp_commit();
    stsA(0, pa);
    cp_wait_all();
    __syncthreads();

    #pragma unroll 1
    for (int c = 0; c < 4; ++c) {
        const int buf = c & 1;
        const int nxt = buf ^ 1;

        if (c < 3) {
            #pragma unroll
            for (int i = 0; i < 4; i++)
                pa[i] = X4[(row0 + amr[i]) * 64 + (c + 1) * 16 + acr[i]];
            stageB(c + 1, nxt); cp_commit();
        }

        const uint32_t* Ab = Asm + buf * (A_BUF / 4);
        const uint32_t* Bb = Bsm + buf * (B_BUF / 4);
        #pragma unroll
        for (int ks = 0; ks < 4; ks++) {
            const int k2b = ks * 8;
            uint32_t a[2][4];
            #pragma unroll
            for (int mt = 0; mt < 2; mt++) {
                int r = warp_m * 32 + mt * 16 + qid;
                a[mt][0] = Ab[r * AS_STRIDE + k2b + qlane];
                a[mt][1] = Ab[(r + 8) * AS_STRIDE + k2b + qlane];
                a[mt][2] = Ab[r * AS_STRIDE + k2b + qlane + 4];
                a[mt][3] = Ab[(r + 8) * AS_STRIDE + k2b + qlane + 4];
            }
            uint32_t b[8][2];
            #pragma unroll
            for (int nt = 0; nt < 8; nt++) {
                int n = warp_n * 64 + nt * 8 + qid;
                b[nt][0] = Bb[(k2b + qlane)     * BS_STRIDE + n];
                b[nt][1] = Bb[(k2b + qlane + 4) * BS_STRIDE + n];
            }
            #pragma unroll
            for (int mt = 0; mt < 2; mt++)
                #pragma unroll
                for (int nt = 0; nt < 8; nt++)
                    mma_bf16(acc[mt][nt], a[mt], b[nt]);
        }

        if (c < 3) {
            stsA(nxt, pa);
            cp_wait_all();
            __syncthreads();
        }
    }

    // Fused epilogue: per-row sum of fast_tanh(u)*proj over warp's 64 cols.
    float psum[2][2];
    psum[0][0] = psum[0][1] = psum[1][0] = psum[1][1] = 0.0f;
    #pragma unroll
    for (int mt = 0; mt < 2; mt++)
        #pragma unroll
        for (int nt = 0; nt < 8; nt++) {
            int cb = warp_n * 64 + nt * 8 + 2 * qlane;
            float p0 = sproj[cb], p1 = sproj[cb + 1];
            psum[mt][0] += fast_tanh(acc[mt][nt][0]) * p0 + fast_tanh(acc[mt][nt][1]) * p1;
            psum[mt][1] += fast_tanh(acc[mt][nt][2]) * p0 + fast_tanh(acc[mt][nt][3]) * p1;
        }
    #pragma unroll
    for (int off = 1; off < 4; off <<= 1) {
        #pragma unroll
        for (int mt = 0; mt < 2; mt++) {
            psum[mt][0] += __shfl_xor_sync(0xffffffffu, psum[mt][0], off);
            psum[mt][1] += __shfl_xor_sync(0xffffffffu, psum[mt][1], off);
        }
    }
    __syncthreads();
    if (qlane == 0) {
        #pragma unroll
        for (int mt = 0; mt < 2; mt++) {
            part[warp_n * 64 + warp_m * 32 + mt * 16 + qid]     = psum[mt][0];
            part[warp_n * 64 + warp_m * 32 + mt * 16 + qid + 8] = psum[mt][1];
        }
    }
    __syncthreads();
    if (tid < 64)
        g_score[row0 + tid] = part[tid] + part[64 + tid] +
                              part[128 + tid] + part[192 + tid];
}

// ---------------------------------------------------------------------------
// Kernel 2: p[j,:] = softmax over N of score[j,:]   (one block per row j)
// ---------------------------------------------------------------------------
__global__ __launch_bounds__(256) void softmax_kernel()
{
    __shared__ float red_max[8];
    __shared__ float red_sum[8];
    const int j   = blockIdx.x;
    const int tid = threadIdx.x;
    const float* row = g_score + j * N_NODE;

    float v[8];
    float m = -1e30f;
    #pragma unroll
    for (int i = 0; i < 8; i++) {
        v[i] = row[tid + i * 256];
        m = fmaxf(m, v[i]);
    }
    #pragma unroll
    for (int off = 16; off > 0; off >>= 1)
        m = fmaxf(m, __shfl_xor_sync(0xffffffffu, m, off));
    if ((tid & 31) == 0) red_max[tid >> 5] = m;
    __syncthreads();
    float bm = red_max[0];
    #pragma unroll
    for (int wq = 1; wq < 8; wq++) bm = fmaxf(bm, red_max[wq]);

    float s = 0.0f;
    #pragma unroll
    for (int i = 0; i < 8; i++) {
        v[i] = expf(v[i] - bm);
        s += v[i];
    }
    #pragma unroll
    for (int off = 16; off > 0; off >>= 1)
        s += __shfl_xor_sync(0xffffffffu, s, off);
    if ((tid & 31) == 0) red_sum[tid >> 5] = s;
    __syncthreads();
    float bs = 0.0f;
    #pragma unroll
    for (int wq = 0; wq < 8; wq++) bs += red_sum[wq];
    float inv = 1.0f / bs;

    #pragma unroll
    for (int i = 0; i < 8; i++)
        g_p[j * N_NODE + tid + i * 256] = v[i] * inv;
}

// ---------------------------------------------------------------------------
// Kernel 3: out (best measured: 78.8 µs — at the traffic floor, FROZEN).
// ---------------------------------------------------------------------------
__global__ __launch_bounds__(256) void out_kernel(
    const float4* __restrict__ X4,
    float4* __restrict__ out4)
{
    const int STRIDE_T = N_NODE * 64;           // float4 per snapshot
    const int i  = blockIdx.x >> 7;             // snapshot 0..127
    const int n  = ((blockIdx.x & 127) << 4) + (threadIdx.x >> 4);
    const int dp = threadIdx.x & 15;
    const int base = (i * N_NODE + n) * 64;

    if (i < WIN) {
        #pragma unroll
        for (int q = 0; q < 4; q++)
            out4[base + dp + q * 16] = X4[base + dp + q * 16];
    } else {
        const int pb = (i - 3) * N_NODE + n;
        const float p0 = g_p[pb];
        const float p1 = g_p[pb + N_NODE];
        const float p2 = g_p[pb + 2 * N_NODE];
        #pragma unroll
        for (int q = 0; q < 4; q++) {
            int d = base + dp + q * 16;
            float4 a = X4[d - 3 * STRIDE_T];
            float4 b = X4[d - 2 * STRIDE_T];
            float4 c = X4[d - 1 * STRIDE_T];
            float4 o;
            o.x = p0 * a.x + p1 * b.x + p2 * c.x;
            o.y = p0 * a.y + p1 * b.y + p2 * c.y;
            o.z = p0 * a.z + p1 * b.z + p2 * c.z;
            o.w = p0 * a.w + p1 * b.w + p2 * c.w;
            out4[d] = o;
        }
    }
}

// ---------------------------------------------------------------------------
extern "C" void kernel_launch(void* const* d_in, const int* in_sizes, int n_in,
                              void* d_out, int out_size)
{
    const float* X    = (const float*)d_in[0];  // (128, 2048, 256)
    const float* W    = (const float*)d_in[1];  // (256, 256)
    const float* proj = (const float*)d_in[2];  // (256, 1)
    float* out        = (float*)d_out;

    cudaFuncSetAttribute(score_kernel,
                         cudaFuncAttributeMaxDynamicSharedMemorySize, SC_SMEM);

    prep_w_kernel<<<128, 256>>>(W);
    score_kernel<<<ROWS / 64, 256, SC_SMEM>>>((const float4*)X, proj);
    softmax_kernel<<<T_SNAP, 256>>>();
    out_kernel<<<T_SNAP * 128, 256>>>((const float4*)X, (float4*)out);
}

// round 17
// speedup vs baseline: 1.1007x; 1.0049x over previous
#include <cuda_runtime.h>
#include <cuda_bf16.h>
#include <cstdint>

// Problem constants (fixed by setup_inputs): T=128, N=2048, D=256, w=3
#define T_SNAP 128
#define N_NODE 2048
#define D_HID  256
#define WIN    3
#define ROWS   (T_SNAP * N_NODE)   // 262144

// Scratch (allocation-free rule: __device__ globals)
__device__ float g_score[ROWS];
__device__ float g_p[ROWS];
// Pre-packed W: g_Wb[kk*256 + n] = bf16x2{ W[2kk][n], W[2kk+1][n] }, kk=0..127
__device__ uint32_t g_Wb[128 * 256];   // 128 KB

// ---------------------------------------------------------------------------
__device__ __forceinline__ uint32_t pack_bf16(float lo, float hi) {
    __nv_bfloat162 h = __floats2bfloat162_rn(lo, hi);
    return *reinterpret_cast<uint32_t*>(&h);
}

// Fast tanh: 1 - 2/(e^{2x}+1). MUFU-based (~6 instr vs ~18 for tanhf).
__device__ __forceinline__ float fast_tanh(float x) {
    float t = __expf(2.0f * x);
    return 1.0f - __fdividef(2.0f, t + 1.0f);
}

__device__ __forceinline__ void mma_bf16(float* c, const uint32_t* a, const uint32_t* b) {
    asm volatile(
        "mma.sync.aligned.m16n8k16.row.col.f32.bf16.bf16.f32 "
        "{%0,%1,%2,%3}, {%4,%5,%6,%7}, {%8,%9}, {%0,%1,%2,%3};"
        : "+f"(c[0]), "+f"(c[1]), "+f"(c[2]), "+f"(c[3])
        : "r"(a[0]), "r"(a[1]), "r"(a[2]), "r"(a[3]), "r"(b[0]), "r"(b[1]));
}

__device__ __forceinline__ void cp_async16(uint32_t smem_dst, const void* gptr) {
    asm volatile("cp.async.cg.shared.global [%0], [%1], 16;"
                 :: "r"(smem_dst), "l"(gptr) : "memory");
}
__device__ __forceinline__ void cp_commit() {
    asm volatile("cp.async.commit_group;" ::: "memory");
}
__device__ __forceinline__ void cp_wait_all() {
    asm volatile("cp.async.wait_group 0;" ::: "memory");
}

// ---------------------------------------------------------------------------
// Kernel 0: pack W into bf16x2 [kk][n] layout (one-shot, ~µs)
// ---------------------------------------------------------------------------
__global__ __launch_bounds__(256) void prep_w_kernel(const float* __restrict__ W)
{
    int idx = blockIdx.x * 256 + threadIdx.x;  // 0..32767
    int n  = idx & 255;
    int kk = idx >> 8;                         // global k-pair 0..127
    g_Wb[idx] = pack_bf16(W[(2 * kk) * D_HID + n], W[(2 * kk + 1) * D_HID + n]);
}

// ---------------------------------------------------------------------------
// Kernel 1 (mma.sync bf16, BEST measured — FROZEN):
//   score[row] = proj . tanh( X[row,:] @ W )
// Block: 256 threads = 8 warps, 2(M) x 4(N). Tile M=64, N=256, BK=64 x 4.
// B via cp.async from pre-packed g_Wb (L2-hot); A LDG->pack->STS overlapped
// with the 64-MMA compute block. 2 CTAs/SM. Fast-tanh epilogue.
// ---------------------------------------------------------------------------
#define AS_STRIDE 36    // u32: banks (36r+q)%32 = (4r+q)%32 all distinct
#define BS_STRIDE 264   // u32: banks (8*qlane+qid)%32 all distinct
#define A_BUF (64 * AS_STRIDE * 4)       // 9216 B
#define B_BUF (32 * BS_STRIDE * 4)       // 33792 B
#define A_OFF    0
#define B_OFF    (2 * A_BUF)             // 18432
#define PROJ_OFF (B_OFF + 2 * B_BUF)     // 86016
#define PART_OFF (PROJ_OFF + 1024)       // 87040
#define SC_SMEM  (PART_OFF + 1024)       // 88064

__global__ __launch_bounds__(256, 2) void score_kernel(
    const float4* __restrict__ X4,
    const float*  __restrict__ proj)
{
    extern __shared__ char smem[];
    const uint32_t sb = (uint32_t)__cvta_generic_to_shared(smem);
    uint32_t* Asm = (uint32_t*)(smem + A_OFF);
    uint32_t* Bsm = (uint32_t*)(smem + B_OFF);
    float* sproj  = (float*)(smem + PROJ_OFF);
    float* part   = (float*)(smem + PART_OFF);   // [4][64]

    const int tid    = threadIdx.x;
    const int lane   = tid & 31;
    const int wid    = tid >> 5;
    const int warp_m = wid >> 2;
    const int warp_n = wid & 3;
    const int qid    = lane >> 2;
    const int qlane  = lane & 3;
    const int row0   = blockIdx.x * 64;

    sproj[tid] = proj[tid];

    // A staging coords: 1024 float4 segments per chunk, 4 per thread
    int amr[4], acr[4];
    #pragma unroll
    for (int i = 0; i < 4; i++) {
        int seg = tid + i * 256;                 // 0..1023
        amr[i] = seg >> 4;                       // row 0..63
        acr[i] = seg & 15;                       // float4-col within chunk
    }

    float acc[2][8][4];
    #pragma unroll
    for (int mt = 0; mt < 2; mt++)
        #pragma unroll
        for (int nt = 0; nt < 8; nt++)
            #pragma unroll
            for (int i = 0; i < 4; i++) acc[mt][nt][i] = 0.0f;

    auto stageB = [&](int c, int bf) {
        #pragma unroll
        for (int i = 0; i < 8; i++) {
            int seg = tid + i * 256;             // 0..2047
            int k2  = seg >> 6;                  // 0..31
            int ng  = seg & 63;                  // float4-col 0..63
            cp_async16(sb + B_OFF + bf * B_BUF + (k2 * BS_STRIDE + ng * 4) * 4,
                       &g_Wb[(c * 32 + k2) * 256 + ng * 4]);
        }
    };
    auto stsA = [&](int bf, const float4* v) {
        #pragma unroll
        for (int i = 0; i < 4; i++) {
            uint2 u;
            u.x = pack_bf16(v[i].x, v[i].y);
            u.y = pack_bf16(v[i].z, v[i].w);
            *reinterpret_cast<uint2*>(
                &Asm[bf * (A_BUF / 4) + amr[i] * AS_STRIDE + acr[i] * 2]) = u;
        }
    };

    // ---- Prologue: stage chunk 0 ----
    float4 pa[4];
    #pragma unroll
    for (int i = 0; i < 4; i++)
        pa[i] = X4[(row0 + amr[i]) * 64 + acr[i]];
    stageB(0, 0); cp_commit();
    stsA(0, pa);
    cp_wait_all();
    __syncthreads();

    #pragma unroll 1
    for (int c = 0; c < 4; ++c) {
        const int buf = c & 1;
        const int nxt = buf ^ 1;

        if (c < 3) {
            #pragma unroll
            for (int i = 0; i < 4; i++)
                pa[i] = X4[(row0 + amr[i]) * 64 + (c + 1) * 16 + acr[i]];
            stageB(c + 1, nxt); cp_commit();
        }

        const uint32_t* Ab = Asm + buf * (A_BUF / 4);
        const uint32_t* Bb = Bsm + buf * (B_BUF / 4);
        #pragma unroll
        for (int ks = 0; ks < 4; ks++) {
            const int k2b = ks * 8;
            uint32_t a[2][4];
            #pragma unroll
            for (int mt = 0; mt < 2; mt++) {
                int r = warp_m * 32 + mt * 16 + qid;
                a[mt][0] = Ab[r * AS_STRIDE + k2b + qlane];
                a[mt][1] = Ab[(r + 8) * AS_STRIDE + k2b + qlane];
                a[mt][2] = Ab[r * AS_STRIDE + k2b + qlane + 4];
                a[mt][3] = Ab[(r + 8) * AS_STRIDE + k2b + qlane + 4];
            }
            uint32_t b[8][2];
            #pragma unroll
            for (int nt = 0; nt < 8; nt++) {
                int n = warp_n * 64 + nt * 8 + qid;
                b[nt][0] = Bb[(k2b + qlane)     * BS_STRIDE + n];
                b[nt][1] = Bb[(k2b + qlane + 4) * BS_STRIDE + n];
            }
            #pragma unroll
            for (int mt = 0; mt < 2; mt++)
                #pragma unroll
                for (int nt = 0; nt < 8; nt++)
                    mma_bf16(acc[mt][nt], a[mt], b[nt]);
        }

        if (c < 3) {
            stsA(nxt, pa);
            cp_wait_all();
            __syncthreads();
        }
    }

    // Fused epilogue: per-row sum of fast_tanh(u)*proj over warp's 64 cols.
    float psum[2][2];
    psum[0][0] = psum[0][1] = psum[1][0] = psum[1][1] = 0.0f;
    #pragma unroll
    for (int mt = 0; mt < 2; mt++)
        #pragma unroll
        for (int nt = 0; nt < 8; nt++) {
            int cb = warp_n * 64 + nt * 8 + 2 * qlane;
            float p0 = sproj[cb], p1 = sproj[cb + 1];
            psum[mt][0] += fast_tanh(acc[mt][nt][0]) * p0 + fast_tanh(acc[mt][nt][1]) * p1;
            psum[mt][1] += fast_tanh(acc[mt][nt][2]) * p0 + fast_tanh(acc[mt][nt][3]) * p1;
        }
    #pragma unroll
    for (int off = 1; off < 4; off <<= 1) {
        #pragma unroll
        for (int mt = 0; mt < 2; mt++) {
            psum[mt][0] += __shfl_xor_sync(0xffffffffu, psum[mt][0], off);
            psum[mt][1] += __shfl_xor_sync(0xffffffffu, psum[mt][1], off);
        }
    }
    __syncthreads();
    if (qlane == 0) {
        #pragma unroll
        for (int mt = 0; mt < 2; mt++) {
            part[warp_n * 64 + warp_m * 32 + mt * 16 + qid]     = psum[mt][0];
            part[warp_n * 64 + warp_m * 32 + mt * 16 + qid + 8] = psum[mt][1];
        }
    }
    __syncthreads();
    if (tid < 64)
        g_score[row0 + tid] = part[tid] + part[64 + tid] +
                              part[128 + tid] + part[192 + tid];
}

// ---------------------------------------------------------------------------
// Kernel 2: p[j,:] = softmax over N of score[j,:]   (one block per row j)
// ---------------------------------------------------------------------------
__global__ __launch_bounds__(256) void softmax_kernel()
{
    __shared__ float red_max[8];
    __shared__ float red_sum[8];
    const int j   = blockIdx.x;
    const int tid = threadIdx.x;
    const float* row = g_score + j * N_NODE;

    float v[8];
    float m = -1e30f;
    #pragma unroll
    for (int i = 0; i < 8; i++) {
        v[i] = row[tid + i * 256];
        m = fmaxf(m, v[i]);
    }
    #pragma unroll
    for (int off = 16; off > 0; off >>= 1)
        m = fmaxf(m, __shfl_xor_sync(0xffffffffu, m, off));
    if ((tid & 31) == 0) red_max[tid >> 5] = m;
    __syncthreads();
    float bm = red_max[0];
    #pragma unroll
    for (int wq = 1; wq < 8; wq++) bm = fmaxf(bm, red_max[wq]);

    float s = 0.0f;
    #pragma unroll
    for (int i = 0; i < 8; i++) {
        v[i] = expf(v[i] - bm);
        s += v[i];
    }
    #pragma unroll
    for (int off = 16; off > 0; off >>= 1)
        s += __shfl_xor_sync(0xffffffffu, s, off);
    if ((tid & 31) == 0) red_sum[tid >> 5] = s;
    __syncthreads();
    float bs = 0.0f;
    #pragma unroll
    for (int wq = 0; wq < 8; wq++) bs += red_sum[wq];
    float inv = 1.0f / bs;

    #pragma unroll
    for (int i = 0; i < 8; i++)
        g_p[j * N_NODE + tid + i * 256] = v[i] * inv;
}

// ---------------------------------------------------------------------------
// Kernel 3: out. Snapshot-aligned blocks; 4 float4/thread at fixed (i,n).
// NEW: output stores use __stcs (STG.CS, evict-first) so the 256 MB of
// write-once data stops flushing the X window out of L2 — X's 3x temporal
// reuse across snapshot waves becomes L2 hits.
// ---------------------------------------------------------------------------
__global__ __launch_bounds__(256) void out_kernel(
    const float4* __restrict__ X4,
    float4* __restrict__ out4)
{
    const int STRIDE_T = N_NODE * 64;           // float4 per snapshot
    const int i  = blockIdx.x >> 7;             // snapshot 0..127
    const int n  = ((blockIdx.x & 127) << 4) + (threadIdx.x >> 4);
    const int dp = threadIdx.x & 15;
    const int base = (i * N_NODE + n) * 64;

    if (i < WIN) {
        #pragma unroll
        for (int q = 0; q < 4; q++)
            __stcs(&out4[base + dp + q * 16], X4[base + dp + q * 16]);
    } else {
        const int pb = (i - 3) * N_NODE + n;
        const float p0 = g_p[pb];
        const float p1 = g_p[pb + N_NODE];
        const float p2 = g_p[pb + 2 * N_NODE];
        #pragma unroll
        for (int q = 0; q < 4; q++) {
            int d = base + dp + q * 16;
            float4 a = X4[d - 3 * STRIDE_T];
            float4 b = X4[d - 2 * STRIDE_T];
            float4 c = X4[d - 1 * STRIDE_T];
            float4 o;
            o.x = p0 * a.x + p1 * b.x + p2 * c.x;
            o.y = p0 * a.y + p1 * b.y + p2 * c.y;
            o.z = p0 * a.z + p1 * b.z + p2 * c.z;
            o.w = p0 * a.w + p1 * b.w + p2 * c.w;
            __stcs(&out4[d], o);
        }
    }
}

// ---------------------------------------------------------------------------
extern "C" void kernel_launch(void* const* d_in, const int* in_sizes, int n_in,
                              void* d_out, int out_size)
{
    const float* X    = (const float*)d_in[0];  // (128, 2048, 256)
    const float* W    = (const float*)d_in[1];  // (256, 256)
    const float* proj = (const float*)d_in[2];  // (256, 1)
    float* out        = (float*)d_out;

    cudaFuncSetAttribute(score_kernel,
                         cudaFuncAttributeMaxDynamicSharedMemorySize, SC_SMEM);

    prep_w_kernel<<<128, 256>>>(W);
    score_kernel<<<ROWS / 64, 256, SC_SMEM>>>((const float4*)X, proj);
    softmax_kernel<<<T_SNAP, 256>>>();
    out_kernel<<<T_SNAP * 128, 256>>>((const float4*)X, (float4*)out);
}